// round 13
// baseline (speedup 1.0000x reference)
#include <cuda_runtime.h>
#include <cuda_bf16.h>
#include <math.h>
#include <stdint.h>

// Problem constants
#define BATCH 32768
#define SNODES 16
#define DIN 128
#define HDIM 64
#define ODIM 32
#define MNODES 16
#define NBATCH_TILE 8           // batches per CTA (128 rows)

// smem word-offsets (u32 units)
#define A_STRIDE 68             // words per A row (272B) — LDSM conflict-free
#define B_STRIDE 136            // words per B kp row (hi/lo u64 interleaved)
#define AHI_W 0                 // 128 x 68 = 8704
#define ALO_W 8704              // 128 x 68 = 8704
#define BI_W  17408             // 64 kp x 136 = 8704
#define W_W   26112             // 8 x (16 w1 | 16 w2) = 256
#define BIAS_W 26368            // 64
#define SMEM_WORDS 26432        // 105728 B
#define SMEM_BYTES (SMEM_WORDS * 4)
// epilogue partial buffer overlays A region: [batch][term][col][g] = 12288 w
#define PART_W 0

// bf16 mma: D(16x8,f32) += A(16x16,row) * B(16x8,col)
#define MMA_BF16(d, a, b0, b1)                                                \
    asm volatile("mma.sync.aligned.m16n8k16.row.col.f32.bf16.bf16.f32 "       \
        "{%0,%1,%2,%3}, {%4,%5,%6,%7}, {%8,%9}, {%0,%1,%2,%3};"               \
        : "+f"((d)[0]), "+f"((d)[1]), "+f"((d)[2]), "+f"((d)[3])              \
        : "r"((a)[0]), "r"((a)[1]), "r"((a)[2]), "r"((a)[3]),                 \
          "r"(b0), "r"(b1))

#define LDSM_X4(r, addr)                                                      \
    asm volatile("ldmatrix.sync.aligned.m8n8.x4.shared.b16 {%0,%1,%2,%3}, [%4];" \
        : "=r"((r)[0]), "=r"((r)[1]), "=r"((r)[2]), "=r"((r)[3]) : "r"(addr))

static __device__ __forceinline__ uint32_t smem_u32(const void* p) {
    uint32_t a;
    asm("{ .reg .u64 t; cvta.to.shared.u64 t, %1; cvt.u32.u64 %0, t; }"
        : "=r"(a) : "l"(p));
    return a;
}

// Scratch (device globals; no allocation allowed)
__device__ uint2 g_wint[64 * 64];                // W bf16 (hi,lo) interleaved
__device__ float g_zs[3 * HDIM * ODIM];          // [st*64+h][o], o-coalesced
__device__ float g_y[(size_t)BATCH * 192];       // per-batch y0|y1|y2 (64 each)
__device__ float g_acc[(size_t)BATCH * ODIM];
__device__ float g_p1[4096 * ODIM];              // per-contract-block sums
__device__ float g_p2[256 * ODIM];
__device__ float g_mean[ODIM];
__device__ float g_scale[ODIM];
__device__ float g_shift[ODIM];

// split fp32 pair -> packed bf16x2 (hi, lo); low 16 bits = first elem.
static __device__ __forceinline__ void cvt_hilo2(float a, float b,
                                                 uint32_t& hi, uint32_t& lo) {
    uint32_t h;
    asm("cvt.rn.bf16x2.f32 %0, %1, %2;" : "=r"(h) : "f"(b), "f"(a));
    float fa = __uint_as_float(h << 16);
    float fb = __uint_as_float(h & 0xffff0000u);
    float ra = a - fa;
    float rb = b - fb;
    asm("cvt.rn.bf16x2.f32 %0, %1, %2;" : "=r"(lo) : "f"(rb), "f"(ra));
    hi = h;
}

static __device__ __forceinline__ float sigmoidf_fast(float v) {
    return 1.f / (1.f + __expf(-v));
}

__global__ void noop_kernel() {}

// ---------------------------------------------------------------------------
// Prep: zs step matrices (o-coalesced) + W bf16 hi/lo interleaved table.
// ---------------------------------------------------------------------------
__global__ void prep_kernel(const float* __restrict__ adj_hidden,
                            const float* __restrict__ fh,
                            const float* __restrict__ W) {
    __shared__ float A[MNODES][MNODES][ODIM];
    __shared__ float dA[MNODES][ODIM];
    __shared__ float d2[MNODES][ODIM];
    int t = threadIdx.x;   // 128 threads

    for (int idx = t; idx < MNODES * MNODES * ODIM; idx += 128)
        ((float*)A)[idx] = 0.f;
    __syncthreads();

    for (int idx = t; idx < 120 * ODIM; idx += 128) {
        int p = idx >> 5, o = idx & 31;
        int i = 0, rem = p;
        while (rem >= (MNODES - 1 - i)) { rem -= (MNODES - 1 - i); i++; }
        int j = i + 1 + rem;
        float v = fmaxf(adj_hidden[idx], 0.f);
        A[i][j][o] = v;
        A[j][i][o] = v;
    }
    __syncthreads();

    for (int idx = t; idx < MNODES * ODIM; idx += 128) {
        int q = idx >> 5, o = idx & 31;
        float s = 0.f;
        #pragma unroll
        for (int m = 0; m < MNODES; m++) s += A[m][q][o];
        dA[q][o] = s;
    }
    __syncthreads();

    for (int idx = t; idx < MNODES * ODIM; idx += 128) {
        int q = idx >> 5, o = idx & 31;
        float s = 0.f;
        #pragma unroll
        for (int p = 0; p < MNODES; p++) s += A[p][q][o] * dA[p][o];
        d2[q][o] = s;
    }
    __syncthreads();

    for (int idx = t; idx < HDIM * ODIM; idx += 128) {
        int h = idx >> 5, o = idx & 31;
        float s0 = 0.f, s1 = 0.f, s2 = 0.f;
        #pragma unroll
        for (int m = 0; m < MNODES; m++) {
            float z = fh[m * (HDIM * ODIM) + h * ODIM + o];
            s0 += z;
            s1 += dA[m][o] * z;
            s2 += d2[m][o] * z;
        }
        g_zs[idx] = s0;
        g_zs[2048 + idx] = s1;
        g_zs[4096 + idx] = s2;
    }

    // W split: g_wint[kp*64+h] = (hi, lo) of pair (W[2kp,h], W[2kp+1,h])
    for (int idx = t; idx < 64 * 64; idx += 128) {
        int kp = idx >> 6, h = idx & 63;
        float w0 = W[(2 * kp) * HDIM + h];
        float w1 = W[(2 * kp + 1) * HDIM + h];
        uint32_t hi, lo;
        cvt_hilo2(w0, w1, hi, lo);
        g_wint[idx] = make_uint2(hi, lo);
    }
}

// ---------------------------------------------------------------------------
// Main: 128x64x128 GEMM tile per CTA, mma.sync bf16 split-precision.
// Term-major MMA order (no accumulator RAW chains); smem-reduced epilogue.
// ---------------------------------------------------------------------------
__global__ void __launch_bounds__(256, 2)
main_kernel(const float* __restrict__ adj, const float* __restrict__ feat,
            const float* __restrict__ b_in) {
    extern __shared__ __align__(16) uint32_t sw[];
    float* smf = (float*)sw;
    int tid = threadIdx.x, wid = tid >> 5, lane = tid & 31;
    int blk = blockIdx.x;

    // ---- stage A = features tile (128 rows x 128 k) as bf16 hi/lo
    {
        const float4* src = (const float4*)(feat + (size_t)blk * 128 * DIN);
        #pragma unroll
        for (int i = 0; i < 16; i++) {
            int idx = tid + i * 256;           // float4 index within tile
            int row = idx >> 5, c = idx & 31;
            float4 v = src[idx];
            uint32_t h0, l0, h1, l1;
            cvt_hilo2(v.x, v.y, h0, l0);
            cvt_hilo2(v.z, v.w, h1, l1);
            int wbase = row * A_STRIDE + 2 * c;
            *(uint2*)&sw[AHI_W + wbase] = make_uint2(h0, h1);
            *(uint2*)&sw[ALO_W + wbase] = make_uint2(l0, l1);
        }
    }
    // ---- stage B interleaved (pure uint4 copy from prep table)
    {
        const uint4* wi4 = (const uint4*)g_wint;
        #pragma unroll
        for (int i = 0; i < 8; i++) {
            int idx4 = tid + i * 256;          // 2048 uint4 total
            int kp = idx4 >> 5, r = idx4 & 31;
            uint4 v = wi4[idx4];
            *(uint4*)&sw[BI_W + kp * B_STRIDE + r * 4] = v;
        }
    }
    if (tid < 64) smf[BIAS_W + tid] = b_in[tid];
    // ---- node weights: w1 = colsum(adj), w2 = adj^T w1   (per batch)
    if (tid < 128) {
        int bg = tid >> 4, q = tid & 15;
        const float* adjb = adj + (size_t)(blk * NBATCH_TILE + bg) * 256;
        float dsum = 0.f;
        #pragma unroll
        for (int s = 0; s < 16; s++) dsum += adjb[s * 16 + q];
        smf[W_W + bg * 32 + q] = dsum;
        __syncwarp();
        float e = 0.f;
        #pragma unroll
        for (int u = 0; u < 16; u++) e += adjb[u * 16 + q] * smf[W_W + bg * 32 + u];
        smf[W_W + bg * 32 + 16 + q] = e;
    }
    __syncthreads();

    // ---- warp-tile MMA: 32 rows x 32 cols per warp
    int warp_m = wid & 3, warp_n = wid >> 2;
    int g = lane >> 2, tig = lane & 3;

    float d[2][4][4];
    #pragma unroll
    for (int mt = 0; mt < 2; mt++)
        #pragma unroll
        for (int nt = 0; nt < 4; nt++)
            #pragma unroll
            for (int r = 0; r < 4; r++) d[mt][nt][r] = 0.f;

    const uint32_t sb = smem_u32(sw);
    const uint32_t a_lane = sb +
        (((warp_m * 32 + (lane & 15)) * A_STRIDE + (lane >> 4) * 4) << 2);
    const int bbase = BI_W + tig * B_STRIDE + (warp_n * 32 + g) * 2;

    #pragma unroll 2
    for (int ks = 0; ks < 8; ks++) {
        uint32_t ah[2][4], al[2][4];
        uint32_t aoff = a_lane + ks * 32;
        LDSM_X4(ah[0], aoff);
        LDSM_X4(ah[1], aoff + (16 * A_STRIDE << 2));
        LDSM_X4(al[0], aoff + (ALO_W << 2));
        LDSM_X4(al[1], aoff + ((ALO_W + 16 * A_STRIDE) << 2));
        int bks = bbase + ks * 8 * B_STRIDE;
        uint2 b0[4], b1[4];
        #pragma unroll
        for (int nt = 0; nt < 4; nt++) {
            b0[nt] = *(const uint2*)&sw[bks + nt * 16];
            b1[nt] = *(const uint2*)&sw[bks + nt * 16 + 4 * B_STRIDE];
        }
        // term-major: 3 groups of 8 MMAs, all-distinct accumulators per group
        #pragma unroll
        for (int nt = 0; nt < 4; nt++)
            #pragma unroll
            for (int mt = 0; mt < 2; mt++)
                MMA_BF16(d[mt][nt], ah[mt], b0[nt].x, b1[nt].x);   // hi*hi
        #pragma unroll
        for (int nt = 0; nt < 4; nt++)
            #pragma unroll
            for (int mt = 0; mt < 2; mt++)
                MMA_BF16(d[mt][nt], ah[mt], b0[nt].y, b1[nt].y);   // hi*lo
        #pragma unroll
        for (int nt = 0; nt < 4; nt++)
            #pragma unroll
            for (int mt = 0; mt < 2; mt++)
                MMA_BF16(d[mt][nt], al[mt], b0[nt].x, b1[nt].x);   // lo*hi
    }

    // ---- epilogue: bias + sigmoid + weighted partials into smem (A overlay)
    __syncthreads();   // all warps done reading A/B fragments
    #pragma unroll
    for (int mt = 0; mt < 2; mt++) {
        int batch = warp_m * 2 + mt;
        float w1g  = smf[W_W + batch * 32 + g];
        float w1g8 = smf[W_W + batch * 32 + g + 8];
        float w2g  = smf[W_W + batch * 32 + 16 + g];
        float w2g8 = smf[W_W + batch * 32 + 24 + g];
        #pragma unroll
        for (int nt = 0; nt < 4; nt++)
            #pragma unroll
            for (int c = 0; c < 2; c++) {
                int col = warp_n * 32 + nt * 8 + tig * 2 + c;
                float bias = smf[BIAS_W + col];
                float vg  = sigmoidf_fast(d[mt][nt][c] + bias);
                float vg8 = sigmoidf_fast(d[mt][nt][c + 2] + bias);
                int base = PART_W + batch * 1536 + col * 8 + g;
                smf[base]        = vg + vg8;
                smf[base + 512]  = w1g * vg + w1g8 * vg8;
                smf[base + 1024] = w2g * vg + w2g8 * vg8;
            }
    }
    __syncthreads();

    // ---- reduce over g (8 contiguous) and write y to global
    {
        const float4* p4 = (const float4*)(smf + PART_W);
        size_t yb = (size_t)blk * (NBATCH_TILE * 192);
        #pragma unroll
        for (int i = 0; i < 6; i++) {
            int idx = tid + i * 256;           // 0..1535 = batch*192 + th
            float4 a = p4[idx * 2];
            float4 b = p4[idx * 2 + 1];
            g_y[yb + idx] = ((a.x + a.y) + (a.z + a.w)) +
                            ((b.x + b.y) + (b.z + b.w));
        }
    }
}

// ---------------------------------------------------------------------------
// Contract: acc[b,o] = sum_th y[b,th] * zs[th,o]  (8 batches per block)
// + per-block partial sum of acc into g_p1 (replaces red1).
// ---------------------------------------------------------------------------
__global__ void __launch_bounds__(256)
contract_kernel() {
    __shared__ float zsm[32 * 196];   // zs transposed [o][th], stride 196
    __shared__ float ysm[8 * 192];
    __shared__ float s[256];
    int tid = threadIdx.x, blk = blockIdx.x;

    for (int idx = tid; idx < 6144; idx += 256) {
        int th = idx >> 5, o = idx & 31;
        zsm[o * 196 + th] = g_zs[idx];
    }
    {
        const float* ysrc = g_y + (size_t)blk * (8 * 192);
        #pragma unroll
        for (int i = 0; i < 6; i++) ysm[tid + i * 256] = ysrc[tid + i * 256];
    }
    __syncthreads();

    int b = tid >> 5, o = tid & 31;
    const float4* y4 = (const float4*)(ysm + b * 192);
    const float4* z4 = (const float4*)(zsm + o * 196);
    float a = 0.f;
    #pragma unroll 12
    for (int q = 0; q < 48; q++) {
        float4 y = y4[q];
        float4 z = z4[q];
        a += y.x * z.x + y.y * z.y + y.z * z.z + y.w * z.w;
    }
    g_acc[(size_t)(blk * 8 + b) * 32 + o] = a;

    // block partial for BN mean (deterministic)
    s[tid] = a;
    __syncthreads();
    if (tid < 32) {
        float tot = 0.f;
        #pragma unroll
        for (int j = 0; j < 8; j++) tot += s[tid + 32 * j];
        g_p1[blk * 32 + tid] = tot;
    }
}

// ---------------------------------------------------------------------------
// BN stat reductions (two-pass variance, deterministic)
// ---------------------------------------------------------------------------
__global__ void red1b_kernel() {
    __shared__ float s[256];
    int t = threadIdx.x;
    int o = t & 31, rg = t >> 5;
    float local = 0.f;
    for (int j = 0; j < 512; j++) local += g_p1[(rg + j * 8) * 32 + o];
    s[t] = local;
    __syncthreads();
    if (t < 32) {
        float tot = 0.f;
        #pragma unroll
        for (int j = 0; j < 8; j++) tot += s[j * 32 + t];
        g_mean[t] = tot * (1.f / (3.f * (float)BATCH));
    }
}

__global__ void red2_kernel() {
    __shared__ float s[256];
    int t = threadIdx.x, blk = blockIdx.x;
    int o = t & 31, rg = t >> 5;
    float mu = g_mean[o];
    float local = 0.f;
    int base = blk * 128;
    #pragma unroll
    for (int j = 0; j < 16; j++) {
        float v = g_acc[(size_t)(base + rg + j * 8) * 32 + o] * (1.f / 3.f) - mu;
        local += v * v;
    }
    s[t] = local;
    __syncthreads();
    if (t < 32) {
        float tot = 0.f;
        #pragma unroll
        for (int j = 0; j < 8; j++) tot += s[j * 32 + t];
        g_p2[blk * 32 + t] = tot;
    }
}

__global__ void red2b_kernel(const float* __restrict__ gamma,
                             const float* __restrict__ beta) {
    __shared__ float s[256];
    int t = threadIdx.x;
    int o = t & 31, rg = t >> 5;
    float local = 0.f;
    #pragma unroll
    for (int j = 0; j < 32; j++) local += g_p2[(rg + j * 8) * 32 + o];
    s[t] = local;
    __syncthreads();
    if (t < 32) {
        float tot = 0.f;
        #pragma unroll
        for (int j = 0; j < 8; j++) tot += s[j * 32 + t];
        float var = tot * (1.f / (float)BATCH);
        float istd = rsqrtf(var + 1e-5f);
        float sc = gamma[t] * istd;
        g_scale[t] = sc;
        g_shift[t] = beta[t] - g_mean[t] * sc;
    }
}

__global__ void fin_kernel(float* __restrict__ out) {
    int idx = blockIdx.x * 256 + threadIdx.x;
    float4 a = ((const float4*)g_acc)[idx];
    int o0 = (idx & 7) << 2;
    float4 r;
    {
        float v = a.x * (1.f / 3.f) * g_scale[o0 + 0] + g_shift[o0 + 0];
        r.x = 1.f / (1.f + __expf(-v));
    }
    {
        float v = a.y * (1.f / 3.f) * g_scale[o0 + 1] + g_shift[o0 + 1];
        r.y = 1.f / (1.f + __expf(-v));
    }
    {
        float v = a.z * (1.f / 3.f) * g_scale[o0 + 2] + g_shift[o0 + 2];
        r.z = 1.f / (1.f + __expf(-v));
    }
    {
        float v = a.w * (1.f / 3.f) * g_scale[o0 + 3] + g_shift[o0 + 3];
        r.w = 1.f / (1.f + __expf(-v));
    }
    ((float4*)out)[idx] = r;
}

// ---------------------------------------------------------------------------
extern "C" void kernel_launch(void* const* d_in, const int* in_sizes, int n_in,
                              void* d_out, int out_size) {
    const float* adj   = (const float*)d_in[0];
    const float* feat  = (const float*)d_in[1];
    const float* W     = (const float*)d_in[2];
    const float* b_in  = (const float*)d_in[3];
    const float* fh    = (const float*)d_in[4];
    const float* ah    = (const float*)d_in[5];
    const float* gamma = (const float*)d_in[6];
    const float* beta  = (const float*)d_in[7];
    float* out = (float*)d_out;

    cudaFuncSetAttribute(main_kernel,
                         cudaFuncAttributeMaxDynamicSharedMemorySize, SMEM_BYTES);

    prep_kernel<<<1, 128>>>(ah, fh, W);
    // two no-ops so main_kernel lands in ncu's capture window (-s 5 -c 1)
    noop_kernel<<<1, 32>>>();
    noop_kernel<<<1, 32>>>();
    main_kernel<<<BATCH / NBATCH_TILE, 256, SMEM_BYTES>>>(adj, feat, b_in);
    contract_kernel<<<BATCH / 8, 256>>>();
    red1b_kernel<<<1, 256>>>();
    red2_kernel<<<256, 256>>>();
    red2b_kernel<<<1, 256>>>(gamma, beta);
    fin_kernel<<<1024, 256>>>(out);
}

// round 14
// speedup vs baseline: 1.0203x; 1.0203x over previous
#include <cuda_runtime.h>
#include <cuda_bf16.h>
#include <math.h>
#include <stdint.h>

// Problem constants
#define BATCH 32768
#define SNODES 16
#define DIN 128
#define HDIM 64
#define ODIM 32
#define MNODES 16
#define NBATCH_TILE 8           // batches per CTA (128 rows)

// smem word-offsets (u32 units)
#define A_STRIDE 68             // words per A row (272B) — LDSM conflict-free
#define B_STRIDE 136            // words per B kp row (hi/lo u64 interleaved)
#define AHI_W 0                 // 128 x 68 = 8704
#define ALO_W 8704              // 128 x 68 = 8704
#define BI_W  17408             // 64 kp x 136 = 8704
#define W_W   26112             // 8 x (16 w1 | 16 w2) = 256
#define BIAS_W 26368            // 64
#define SMEM_WORDS 26432        // 105728 B
#define SMEM_BYTES (SMEM_WORDS * 4)
// epilogue partial buffer overlays A region: [batch][term][col][g] = 12288 w
#define PART_W 0

// bf16 mma: D(16x8,f32) += A(16x16,row) * B(16x8,col)
#define MMA_BF16(d, a, b0, b1)                                                \
    asm volatile("mma.sync.aligned.m16n8k16.row.col.f32.bf16.bf16.f32 "       \
        "{%0,%1,%2,%3}, {%4,%5,%6,%7}, {%8,%9}, {%0,%1,%2,%3};"               \
        : "+f"((d)[0]), "+f"((d)[1]), "+f"((d)[2]), "+f"((d)[3])              \
        : "r"((a)[0]), "r"((a)[1]), "r"((a)[2]), "r"((a)[3]),                 \
          "r"(b0), "r"(b1))

#define LDSM_X4(r, addr)                                                      \
    asm volatile("ldmatrix.sync.aligned.m8n8.x4.shared.b16 {%0,%1,%2,%3}, [%4];" \
        : "=r"((r)[0]), "=r"((r)[1]), "=r"((r)[2]), "=r"((r)[3]) : "r"(addr))

static __device__ __forceinline__ uint32_t smem_u32(const void* p) {
    uint32_t a;
    asm("{ .reg .u64 t; cvta.to.shared.u64 t, %1; cvt.u32.u64 %0, t; }"
        : "=r"(a) : "l"(p));
    return a;
}

// Scratch (device globals; no allocation allowed)
__device__ uint2 g_wint[64 * 64];                // W bf16 (hi,lo) interleaved
__device__ float g_zs[3 * HDIM * ODIM];          // [st*64+h][o], o-coalesced
__device__ float g_y[(size_t)BATCH * 192];       // per-batch y0|y1|y2 (64 each)
__device__ float g_acc[(size_t)BATCH * ODIM];
__device__ float g_p1[4096 * ODIM];              // per-contract-block sums
__device__ float g_p2[256 * ODIM];
__device__ float g_mean[ODIM];
__device__ float g_scale[ODIM];
__device__ float g_shift[ODIM];

// split fp32 pair -> packed bf16x2 (hi, lo); low 16 bits = first elem.
static __device__ __forceinline__ void cvt_hilo2(float a, float b,
                                                 uint32_t& hi, uint32_t& lo) {
    uint32_t h;
    asm("cvt.rn.bf16x2.f32 %0, %1, %2;" : "=r"(h) : "f"(b), "f"(a));
    float fa = __uint_as_float(h << 16);
    float fb = __uint_as_float(h & 0xffff0000u);
    float ra = a - fa;
    float rb = b - fb;
    asm("cvt.rn.bf16x2.f32 %0, %1, %2;" : "=r"(lo) : "f"(rb), "f"(ra));
    hi = h;
}

static __device__ __forceinline__ float sigmoidf_fast(float v) {
    return 1.f / (1.f + __expf(-v));
}

__global__ void noop_kernel() {}

// ---------------------------------------------------------------------------
// Prep: zs step matrices (o-coalesced) + W bf16 hi/lo interleaved table.
// ---------------------------------------------------------------------------
__global__ void prep_kernel(const float* __restrict__ adj_hidden,
                            const float* __restrict__ fh,
                            const float* __restrict__ W) {
    __shared__ float A[MNODES][MNODES][ODIM];
    __shared__ float dA[MNODES][ODIM];
    __shared__ float d2[MNODES][ODIM];
    int t = threadIdx.x;   // 128 threads

    for (int idx = t; idx < MNODES * MNODES * ODIM; idx += 128)
        ((float*)A)[idx] = 0.f;
    __syncthreads();

    for (int idx = t; idx < 120 * ODIM; idx += 128) {
        int p = idx >> 5, o = idx & 31;
        int i = 0, rem = p;
        while (rem >= (MNODES - 1 - i)) { rem -= (MNODES - 1 - i); i++; }
        int j = i + 1 + rem;
        float v = fmaxf(adj_hidden[idx], 0.f);
        A[i][j][o] = v;
        A[j][i][o] = v;
    }
    __syncthreads();

    for (int idx = t; idx < MNODES * ODIM; idx += 128) {
        int q = idx >> 5, o = idx & 31;
        float s = 0.f;
        #pragma unroll
        for (int m = 0; m < MNODES; m++) s += A[m][q][o];
        dA[q][o] = s;
    }
    __syncthreads();

    for (int idx = t; idx < MNODES * ODIM; idx += 128) {
        int q = idx >> 5, o = idx & 31;
        float s = 0.f;
        #pragma unroll
        for (int p = 0; p < MNODES; p++) s += A[p][q][o] * dA[p][o];
        d2[q][o] = s;
    }
    __syncthreads();

    for (int idx = t; idx < HDIM * ODIM; idx += 128) {
        int h = idx >> 5, o = idx & 31;
        float s0 = 0.f, s1 = 0.f, s2 = 0.f;
        #pragma unroll
        for (int m = 0; m < MNODES; m++) {
            float z = fh[m * (HDIM * ODIM) + h * ODIM + o];
            s0 += z;
            s1 += dA[m][o] * z;
            s2 += d2[m][o] * z;
        }
        g_zs[idx] = s0;
        g_zs[2048 + idx] = s1;
        g_zs[4096 + idx] = s2;
    }

    // W split: g_wint[kp*64+h] = (hi, lo) of pair (W[2kp,h], W[2kp+1,h])
    for (int idx = t; idx < 64 * 64; idx += 128) {
        int kp = idx >> 6, h = idx & 63;
        float w0 = W[(2 * kp) * HDIM + h];
        float w1 = W[(2 * kp + 1) * HDIM + h];
        uint32_t hi, lo;
        cvt_hilo2(w0, w1, hi, lo);
        g_wint[idx] = make_uint2(hi, lo);
    }
}

// ---------------------------------------------------------------------------
// Main: 128x64x128 GEMM tile per CTA, 512 threads / 16 warps.
// Warp tile 16x32 (one batch per warp_m, warp_n in {0,1}).
// mma.sync bf16 split-precision (hi*hi + hi*lo + lo*hi, fp32 accumulate).
// ---------------------------------------------------------------------------
__global__ void __launch_bounds__(512, 2)
main_kernel(const float* __restrict__ adj, const float* __restrict__ feat,
            const float* __restrict__ b_in) {
    extern __shared__ __align__(16) uint32_t sw[];
    float* smf = (float*)sw;
    int tid = threadIdx.x, wid = tid >> 5, lane = tid & 31;
    int blk = blockIdx.x;

    // ---- stage A = features tile (128 rows x 128 k) as bf16 hi/lo
    {
        const float4* src = (const float4*)(feat + (size_t)blk * 128 * DIN);
        #pragma unroll
        for (int i = 0; i < 8; i++) {
            int idx = tid + i * 512;           // float4 index within tile
            int row = idx >> 5, c = idx & 31;
            float4 v = src[idx];
            uint32_t h0, l0, h1, l1;
            cvt_hilo2(v.x, v.y, h0, l0);
            cvt_hilo2(v.z, v.w, h1, l1);
            int wbase = row * A_STRIDE + 2 * c;
            *(uint2*)&sw[AHI_W + wbase] = make_uint2(h0, h1);
            *(uint2*)&sw[ALO_W + wbase] = make_uint2(l0, l1);
        }
    }
    // ---- stage B interleaved (pure uint4 copy from prep table)
    {
        const uint4* wi4 = (const uint4*)g_wint;
        #pragma unroll
        for (int i = 0; i < 4; i++) {
            int idx4 = tid + i * 512;          // 2048 uint4 total
            int kp = idx4 >> 5, r = idx4 & 31;
            uint4 v = wi4[idx4];
            *(uint4*)&sw[BI_W + kp * B_STRIDE + r * 4] = v;
        }
    }
    if (tid < 64) smf[BIAS_W + tid] = b_in[tid];
    // ---- node weights: w1 = colsum(adj), w2 = adj^T w1   (per batch)
    if (tid < 128) {
        int bg = tid >> 4, q = tid & 15;
        const float* adjb = adj + (size_t)(blk * NBATCH_TILE + bg) * 256;
        float dsum = 0.f;
        #pragma unroll
        for (int s = 0; s < 16; s++) dsum += adjb[s * 16 + q];
        smf[W_W + bg * 32 + q] = dsum;
        __syncwarp();
        float e = 0.f;
        #pragma unroll
        for (int u = 0; u < 16; u++) e += adjb[u * 16 + q] * smf[W_W + bg * 32 + u];
        smf[W_W + bg * 32 + 16 + q] = e;
    }
    __syncthreads();

    // ---- warp-tile MMA: 16 rows (one batch) x 32 cols per warp
    int warp_m = wid & 7, warp_n = wid >> 3;
    int g = lane >> 2, tig = lane & 3;

    float d[4][4];
    #pragma unroll
    for (int nt = 0; nt < 4; nt++)
        #pragma unroll
        for (int r = 0; r < 4; r++) d[nt][r] = 0.f;

    const uint32_t sb = smem_u32(sw);
    const uint32_t a_lane = sb +
        (((warp_m * 16 + (lane & 15)) * A_STRIDE + (lane >> 4) * 4) << 2);
    const int bbase = BI_W + tig * B_STRIDE + (warp_n * 32 + g) * 2;

    #pragma unroll 2
    for (int ks = 0; ks < 8; ks++) {
        uint32_t ah[4], al[4];
        uint32_t aoff = a_lane + ks * 32;
        LDSM_X4(ah, aoff);
        LDSM_X4(al, aoff + (ALO_W << 2));
        int bks = bbase + ks * 8 * B_STRIDE;
        uint2 b0[4], b1[4];
        #pragma unroll
        for (int nt = 0; nt < 4; nt++) {
            b0[nt] = *(const uint2*)&sw[bks + nt * 16];
            b1[nt] = *(const uint2*)&sw[bks + nt * 16 + 4 * B_STRIDE];
        }
        #pragma unroll
        for (int nt = 0; nt < 4; nt++)
            MMA_BF16(d[nt], ah, b0[nt].x, b1[nt].x);   // hi*hi
        #pragma unroll
        for (int nt = 0; nt < 4; nt++)
            MMA_BF16(d[nt], ah, b0[nt].y, b1[nt].y);   // hi*lo
        #pragma unroll
        for (int nt = 0; nt < 4; nt++)
            MMA_BF16(d[nt], al, b0[nt].x, b1[nt].x);   // lo*hi
    }

    // ---- epilogue: bias + sigmoid + weighted partials into smem (A overlay)
    __syncthreads();   // all warps done reading A/B fragments
    {
        int batch = warp_m;
        float w1g  = smf[W_W + batch * 32 + g];
        float w1g8 = smf[W_W + batch * 32 + g + 8];
        float w2g  = smf[W_W + batch * 32 + 16 + g];
        float w2g8 = smf[W_W + batch * 32 + 24 + g];
        #pragma unroll
        for (int nt = 0; nt < 4; nt++)
            #pragma unroll
            for (int c = 0; c < 2; c++) {
                int col = warp_n * 32 + nt * 8 + tig * 2 + c;
                float bias = smf[BIAS_W + col];
                float vg  = sigmoidf_fast(d[nt][c] + bias);
                float vg8 = sigmoidf_fast(d[nt][c + 2] + bias);
                int base = PART_W + batch * 1536 + col * 8 + g;
                smf[base]        = vg + vg8;
                smf[base + 512]  = w1g * vg + w1g8 * vg8;
                smf[base + 1024] = w2g * vg + w2g8 * vg8;
            }
    }
    __syncthreads();

    // ---- reduce over g (8 contiguous) and write y to global
    {
        const float4* p4 = (const float4*)(smf + PART_W);
        size_t yb = (size_t)blk * (NBATCH_TILE * 192);
        #pragma unroll
        for (int i = 0; i < 3; i++) {
            int idx = tid + i * 512;           // 0..1535 = batch*192 + th
            float4 a = p4[idx * 2];
            float4 b = p4[idx * 2 + 1];
            g_y[yb + idx] = ((a.x + a.y) + (a.z + a.w)) +
                            ((b.x + b.y) + (b.z + b.w));
        }
    }
}

// ---------------------------------------------------------------------------
// Contract: acc[b,o] = sum_th y[b,th] * zs[th,o]  (8 batches per block)
// + per-block partial sum of acc into g_p1 (replaces red1).
// ---------------------------------------------------------------------------
__global__ void __launch_bounds__(256)
contract_kernel() {
    __shared__ float zsm[32 * 196];   // zs transposed [o][th], stride 196
    __shared__ float ysm[8 * 192];
    __shared__ float s[256];
    int tid = threadIdx.x, blk = blockIdx.x;

    for (int idx = tid; idx < 6144; idx += 256) {
        int th = idx >> 5, o = idx & 31;
        zsm[o * 196 + th] = g_zs[idx];
    }
    {
        const float* ysrc = g_y + (size_t)blk * (8 * 192);
        #pragma unroll
        for (int i = 0; i < 6; i++) ysm[tid + i * 256] = ysrc[tid + i * 256];
    }
    __syncthreads();

    int b = tid >> 5, o = tid & 31;
    const float4* y4 = (const float4*)(ysm + b * 192);
    const float4* z4 = (const float4*)(zsm + o * 196);
    float a = 0.f;
    #pragma unroll 12
    for (int q = 0; q < 48; q++) {
        float4 y = y4[q];
        float4 z = z4[q];
        a += y.x * z.x + y.y * z.y + y.z * z.z + y.w * z.w;
    }
    g_acc[(size_t)(blk * 8 + b) * 32 + o] = a;

    // block partial for BN mean (deterministic)
    s[tid] = a;
    __syncthreads();
    if (tid < 32) {
        float tot = 0.f;
        #pragma unroll
        for (int j = 0; j < 8; j++) tot += s[tid + 32 * j];
        g_p1[blk * 32 + tid] = tot;
    }
}

// ---------------------------------------------------------------------------
// BN stat reductions (two-pass variance, deterministic)
// ---------------------------------------------------------------------------
__global__ void red1b_kernel() {
    __shared__ float s[256];
    int t = threadIdx.x;
    int o = t & 31, rg = t >> 5;
    float local = 0.f;
    for (int j = 0; j < 512; j++) local += g_p1[(rg + j * 8) * 32 + o];
    s[t] = local;
    __syncthreads();
    if (t < 32) {
        float tot = 0.f;
        #pragma unroll
        for (int j = 0; j < 8; j++) tot += s[j * 32 + t];
        g_mean[t] = tot * (1.f / (3.f * (float)BATCH));
    }
}

__global__ void red2_kernel() {
    __shared__ float s[256];
    int t = threadIdx.x, blk = blockIdx.x;
    int o = t & 31, rg = t >> 5;
    float mu = g_mean[o];
    float local = 0.f;
    int base = blk * 128;
    #pragma unroll
    for (int j = 0; j < 16; j++) {
        float v = g_acc[(size_t)(base + rg + j * 8) * 32 + o] * (1.f / 3.f) - mu;
        local += v * v;
    }
    s[t] = local;
    __syncthreads();
    if (t < 32) {
        float tot = 0.f;
        #pragma unroll
        for (int j = 0; j < 8; j++) tot += s[j * 32 + t];
        g_p2[blk * 32 + t] = tot;
    }
}

__global__ void red2b_kernel(const float* __restrict__ gamma,
                             const float* __restrict__ beta) {
    __shared__ float s[256];
    int t = threadIdx.x;
    int o = t & 31, rg = t >> 5;
    float local = 0.f;
    #pragma unroll
    for (int j = 0; j < 32; j++) local += g_p2[(rg + j * 8) * 32 + o];
    s[t] = local;
    __syncthreads();
    if (t < 32) {
        float tot = 0.f;
        #pragma unroll
        for (int j = 0; j < 8; j++) tot += s[j * 32 + t];
        float var = tot * (1.f / (float)BATCH);
        float istd = rsqrtf(var + 1e-5f);
        float sc = gamma[t] * istd;
        g_scale[t] = sc;
        g_shift[t] = beta[t] - g_mean[t] * sc;
    }
}

__global__ void fin_kernel(float* __restrict__ out) {
    int idx = blockIdx.x * 256 + threadIdx.x;
    float4 a = ((const float4*)g_acc)[idx];
    int o0 = (idx & 7) << 2;
    float4 r;
    {
        float v = a.x * (1.f / 3.f) * g_scale[o0 + 0] + g_shift[o0 + 0];
        r.x = 1.f / (1.f + __expf(-v));
    }
    {
        float v = a.y * (1.f / 3.f) * g_scale[o0 + 1] + g_shift[o0 + 1];
        r.y = 1.f / (1.f + __expf(-v));
    }
    {
        float v = a.z * (1.f / 3.f) * g_scale[o0 + 2] + g_shift[o0 + 2];
        r.z = 1.f / (1.f + __expf(-v));
    }
    {
        float v = a.w * (1.f / 3.f) * g_scale[o0 + 3] + g_shift[o0 + 3];
        r.w = 1.f / (1.f + __expf(-v));
    }
    ((float4*)out)[idx] = r;
}

// ---------------------------------------------------------------------------
extern "C" void kernel_launch(void* const* d_in, const int* in_sizes, int n_in,
                              void* d_out, int out_size) {
    const float* adj   = (const float*)d_in[0];
    const float* feat  = (const float*)d_in[1];
    const float* W     = (const float*)d_in[2];
    const float* b_in  = (const float*)d_in[3];
    const float* fh    = (const float*)d_in[4];
    const float* ah    = (const float*)d_in[5];
    const float* gamma = (const float*)d_in[6];
    const float* beta  = (const float*)d_in[7];
    float* out = (float*)d_out;

    cudaFuncSetAttribute(main_kernel,
                         cudaFuncAttributeMaxDynamicSharedMemorySize, SMEM_BYTES);

    prep_kernel<<<1, 128>>>(ah, fh, W);
    // two no-ops so main_kernel lands in ncu's capture window (-s 5 -c 1)
    noop_kernel<<<1, 32>>>();
    noop_kernel<<<1, 32>>>();
    main_kernel<<<BATCH / NBATCH_TILE, 512, SMEM_BYTES>>>(adj, feat, b_in);
    contract_kernel<<<BATCH / 8, 256>>>();
    red1b_kernel<<<1, 256>>>();
    red2_kernel<<<256, 256>>>();
    red2b_kernel<<<1, 256>>>(gamma, beta);
    fin_kernel<<<1024, 256>>>(out);
}